// round 8
// baseline (speedup 1.0000x reference)
#include <cuda_runtime.h>
#include <math.h>

#define ETA 0.1f
#define THETA 4.0f
#define NN 4096            // 64*64
#define MATS_PER_CTA 3
#define THREADS 192        // 3 matrices per CTA, 64 threads each
#define MAX_BATCH 8192

typedef unsigned long long u64;

// global scratch: E1 (= scaled A) and A3 per matrix
__device__ float g_scrA [(size_t)MAX_BATCH * NN];
__device__ float g_scrA3[(size_t)MAX_BATCH * NN];

__device__ __forceinline__ u64 fma2(u64 a, u64 b, u64 c) {
    u64 d;
    asm("fma.rn.f32x2 %0, %1, %2, %3;" : "=l"(d) : "l"(a), "l"(b), "l"(c));
    return d;
}
__device__ __forceinline__ u64 dup2(float a) {
    u64 d;
    asm("mov.b64 %0, {%1, %1};" : "=l"(d) : "f"(a));
    return d;
}
__device__ __forceinline__ float2 unpk(u64 v) {
    float2 r;
    asm("mov.b64 {%0, %1}, %2;" : "=f"(r.x), "=f"(r.y) : "l"(v));
    return r;
}

// per-matrix barrier (64 threads = 2 warps), compile-time immediate id
__device__ __forceinline__ void hbar(int m) {
    if (m == 0)      asm volatile("bar.sync 1, 64;" ::: "memory");
    else if (m == 1) asm volatile("bar.sync 2, 64;" ::: "memory");
    else             asm volatile("bar.sync 3, 64;" ::: "memory");
}

// swizzled float offset of logical (row, float4-chunk). chunk in [0,16).
__device__ __forceinline__ int sw(int r, int c) {
    return (r << 6) + ((c ^ ((r >> 2) & 6)) << 2);
}

__global__ void __launch_bounds__(THREADS, 1)
meg_update_kernel(const float* __restrict__ gR,
                  const float* __restrict__ gG,
                  float* __restrict__ gOut, int batch) {
    const int tid = threadIdx.x;
    const int m = tid >> 6;          // which matrix of this CTA
    const int t = tid & 63;

    const int gmat = blockIdx.x * MATS_PER_CTA + m;
    if (gmat >= batch) return;       // tail CTA: whole warp-pair exits

    extern __shared__ float smx[];
    float* s0 = smx + m * 4 * NN;    // A, later S2 ping-pong
    float* s1 = s0 + 1 * NN;         // A2 (and E2)
    float* s2 = s0 + 2 * NN;         // A4
    float* s3 = s0 + 3 * NN;         // S ping-pong

    float* gE1 = g_scrA  + (size_t)gmat * NN;   // scaled A
    float* gE3 = g_scrA3 + (size_t)gmat * NN;   // A3

    __shared__ float s_red[MATS_PER_CTA][2];
    __shared__ int   s_nsq[MATS_PER_CTA];

    const size_t gbase = (size_t)gmat * NN;
    const float4* R4 = (const float4*)(gR + gbase);
    const float4* G4 = (const float4*)(gG + gbase);
    float4* O4 = (float4*)(gOut + gbase);

    // ---- load G (swizzled) into s3 ----
#pragma unroll
    for (int q = 0; q < 16; q++) {
        const int e4 = t + q * 64;
        const int r = e4 >> 4, c4 = e4 & 15;
        *(float4*)(s3 + sw(r, c4)) = G4[e4];
    }
    hbar(m);

    // ---- A = log(R) - ETA*(G - G^T) -> s0 ----
#pragma unroll
    for (int q = 0; q < 16; q++) {
        const int e4 = t + q * 64;
        const int r = e4 >> 4, c4 = e4 & 15;
        const int cb = c4 << 2;
        const float4 rv = R4[e4];
        const float4 gv = *(const float4*)(s3 + sw(r, c4));
        const float gt0 = s3[sw(cb + 0, r >> 2) + (r & 3)];
        const float gt1 = s3[sw(cb + 1, r >> 2) + (r & 3)];
        const float gt2 = s3[sw(cb + 2, r >> 2) + (r & 3)];
        const float gt3 = s3[sw(cb + 3, r >> 2) + (r & 3)];
        float4 a;
        a.x = logf(rv.x) - ETA * (gv.x - gt0);
        a.y = logf(rv.y) - ETA * (gv.y - gt1);
        a.z = logf(rv.z) - ETA * (gv.z - gt2);
        a.w = logf(rv.w) - ETA * (gv.w - gt3);
        *(float4*)(s0 + sw(r, c4)) = a;
    }
    hbar(m);

    // ---- inf-norm: thread t owns row t ----
    {
        float rs = 0.0f;
#pragma unroll
        for (int c = 0; c < 16; c++) {
            const float4 v = *(const float4*)(s0 + sw(t, c));
            rs += fabsf(v.x) + fabsf(v.y) + fabsf(v.z) + fabsf(v.w);
        }
#pragma unroll
        for (int o = 16; o > 0; o >>= 1)
            rs = fmaxf(rs, __shfl_xor_sync(0xffffffffu, rs, o));
        if ((t & 31) == 0) s_red[m][t >> 5] = rs;
        hbar(m);
        if (t == 0) {
            const float nrm = fmaxf(s_red[m][0], s_red[m][1]);
            int s = 0;
            if (nrm > THETA && isfinite(nrm)) {
                s = (int)ceilf(log2f(nrm / THETA));
                if (s < 0) s = 0;
                if (s > 30) s = 30;
            }
            s_nsq[m] = s;
        }
        hbar(m);
    }
    const int nsq = s_nsq[m];
    const float scale = exp2f((float)-nsq);

    // ---- scale A in s0; also persist scaled A to global (E1) ----
#pragma unroll
    for (int q = 0; q < 16; q++) {
        float4* p = (float4*)s0 + (t + q * 64);
        float4 v = *p;
        v.x *= scale; v.y *= scale; v.z *= scale; v.w *= scale;
        *p = v;
        ((float4*)gE1)[t + q * 64] = v;   // same swizzled layout in global
    }
    __threadfence_block();
    hbar(m);

    // Taylor 1/k! coefficients
    const float c0  = 1.0f, c1 = 1.0f, c2 = 0.5f;
    const float c3  = (float)(1.0 / 6.0),            c4c = (float)(1.0 / 24.0);
    const float c5  = (float)(1.0 / 120.0),          c6 = (float)(1.0 / 720.0);
    const float c7  = (float)(1.0 / 5040.0),         c8 = (float)(1.0 / 40320.0);
    const float c9  = (float)(1.0 / 362880.0),       c10 = (float)(1.0 / 3628800.0);
    const float c11 = (float)(1.0 / 39916800.0),     c12 = (float)(1.0 / 479001600.0);
    const float c13 = (float)(1.0 / 6227020800.0),   c14 = (float)(1.0 / 87178291200.0);
    const float c15 = (float)(1.0 / 1307674368000.0);
    const float c16 = (float)(1.0 / 20922789888000.0);

    // ---- unified GEMM step loop ----
    const int ty = t >> 3, tx = t & 7;
    const int r0 = ty << 3;
    const int sA = (ty & 3) << 1;
    const int sc = tx ^ sA;

    const int nsteps = 6 + nsq;
#pragma unroll 1
    for (int step = 0; step < nsteps; step++) {
        // --- pointer / coefficient selection (uniform) ---
        float* C; const float* A; const float* B;
        float d0 = 0.f, d1 = 0.f, d2 = 0.f, d3 = 0.f;
        bool epi = false, toGlobal = false;
        if (step == 0)      { C = s1; A = s0; B = s0; }            // A2
        else if (step == 1) { C = s1; A = s1; B = s0; toGlobal = true; }  // A3 -> global
        else if (step == 2) { C = s2; A = s1; B = s1; }            // A4
        else if (step < 6) {
            const int h = step - 3;
            A = s2;
            if (h == 1) { B = s0; C = s3; }
            else        { B = s3; C = s0; }
            epi = true;
            d0 = (h == 0) ? c8  : (h == 1) ? c4c : c0;
            d1 = (h == 0) ? c9  : (h == 1) ? c5  : c1;
            d2 = (h == 0) ? c10 : (h == 1) ? c6  : c2;
            d3 = (h == 0) ? c11 : (h == 1) ? c7  : c3;
        } else {
            if (((step - 6) & 1) == 0) { A = s0; B = s0; C = s3; }
            else                       { A = s3; B = s3; C = s0; }
        }

        // --- seed S (-> s3) after powers are ready, before first Horner ---
        if (step == 3) {
#pragma unroll
            for (int q = 0; q < 16; q++) {
                const int e4 = t + q * 64;
                const int r = e4 >> 4, c4 = e4 & 15;
                const int off = sw(r, c4);
                const float4 a  = *(const float4*)(s0 + off);
                const float4 a2 = *(const float4*)(s1 + off);
                const float4 a3 = ((const float4*)gE3)[e4];
                const float4 a4 = *(const float4*)(s2 + off);
                float4 s;
                s.x = fmaf(c13, a.x, fmaf(c14, a2.x, fmaf(c15, a3.x, c16 * a4.x)));
                s.y = fmaf(c13, a.y, fmaf(c14, a2.y, fmaf(c15, a3.y, c16 * a4.y)));
                s.z = fmaf(c13, a.z, fmaf(c14, a2.z, fmaf(c15, a3.z, c16 * a4.z)));
                s.w = fmaf(c13, a.w, fmaf(c14, a2.w, fmaf(c15, a3.w, c16 * a4.w)));
                if ((r >> 2) == c4) ((float*)&s)[r & 3] += c12;
                *(float4*)(s3 + off) = s;
            }
            hbar(m);
        }

        // --- the single GEMM instance ---
        u64 acc[8][4];
#pragma unroll
        for (int i = 0; i < 8; i++) { acc[i][0] = acc[i][1] = acc[i][2] = acc[i][3] = 0ull; }

        float4 av[2][8];
        ulonglong2 bv[2][2];

#define AVLOAD(buf, cc) do {                                                       \
        const int ao_ = (((cc) ^ sA) << 2);                                        \
        _Pragma("unroll")                                                          \
        for (int i_ = 0; i_ < 8; i_++)                                             \
            av[buf][i_] = *(const float4*)(A + ((r0 + i_) << 6) + ao_);            \
    } while (0)

#define BVLOAD(buf, K) do {                                                        \
        const int kr_ = (K) < 63 ? (K) : 63;                                       \
        const int bo_ = ((tx ^ ((kr_ >> 2) & 6)) << 2);                            \
        const float* br_ = B + (kr_ << 6);                                         \
        bv[buf][0] = *(const ulonglong2*)(br_ + bo_);                              \
        bv[buf][1] = *(const ulonglong2*)(br_ + bo_ + 32);                         \
    } while (0)

#define MMCOMP(ab, bb, kk) do {                                                    \
        _Pragma("unroll")                                                          \
        for (int i_ = 0; i_ < 8; i_++) {                                           \
            const float a_ = ((const float*)&av[ab][i_])[kk];                      \
            const u64 aa_ = dup2(a_);                                              \
            acc[i_][0] = fma2(aa_, bv[bb][0].x, acc[i_][0]);                       \
            acc[i_][1] = fma2(aa_, bv[bb][0].y, acc[i_][1]);                       \
            acc[i_][2] = fma2(aa_, bv[bb][1].x, acc[i_][2]);                       \
            acc[i_][3] = fma2(aa_, bv[bb][1].y, acc[i_][3]);                       \
        }                                                                          \
    } while (0)

#define CHUNK(ab, Kbase) do {                                                      \
        BVLOAD(1, (Kbase) + 1); MMCOMP(ab, 0, 0);                                  \
        BVLOAD(0, (Kbase) + 2); MMCOMP(ab, 1, 1);                                  \
        BVLOAD(1, (Kbase) + 3); MMCOMP(ab, 0, 2);                                  \
        BVLOAD(0, (Kbase) + 4); MMCOMP(ab, 1, 3);                                  \
    } while (0)

        AVLOAD(0, 0);
        BVLOAD(0, 0);
#pragma unroll 1
        for (int b = 0; b < 8; b++) {
            const int cc = 2 * b;
            AVLOAD(1, cc + 1);
            CHUNK(0, cc * 4);
            const int nc = (cc + 2 < 15) ? (cc + 2) : 15;
            AVLOAD(0, nc);
            CHUNK(1, (cc + 1) * 4);
        }

#undef AVLOAD
#undef BVLOAD
#undef MMCOMP
#undef CHUNK

        // --- epilogue + store ---
#pragma unroll
        for (int i = 0; i < 8; i++) {
            const int row = r0 + i;
            const int offL = (row << 6) + (sc << 2);
            const int offH = offL + 32;
            const float2 p0 = unpk(acc[i][0]), p1 = unpk(acc[i][1]);
            const float2 p2 = unpk(acc[i][2]), p3 = unpk(acc[i][3]);
            float4 o0 = make_float4(p0.x, p0.y, p1.x, p1.y);
            float4 o1 = make_float4(p2.x, p2.y, p3.x, p3.y);
            if (epi) {
                const float4 e1L = *(const float4*)(gE1 + offL);   // global
                const float4 e2L = *(const float4*)(s1  + offL);   // smem
                const float4 e3L = *(const float4*)(gE3 + offL);   // global
                const float4 e1H = *(const float4*)(gE1 + offH);
                const float4 e2H = *(const float4*)(s1  + offH);
                const float4 e3H = *(const float4*)(gE3 + offH);
                o0.x += fmaf(d1, e1L.x, fmaf(d2, e2L.x, d3 * e3L.x));
                o0.y += fmaf(d1, e1L.y, fmaf(d2, e2L.y, d3 * e3L.y));
                o0.z += fmaf(d1, e1L.z, fmaf(d2, e2L.z, d3 * e3L.z));
                o0.w += fmaf(d1, e1L.w, fmaf(d2, e2L.w, d3 * e3L.w));
                o1.x += fmaf(d1, e1H.x, fmaf(d2, e2H.x, d3 * e3H.x));
                o1.y += fmaf(d1, e1H.y, fmaf(d2, e2H.y, d3 * e3H.y));
                o1.z += fmaf(d1, e1H.z, fmaf(d2, e2H.z, d3 * e3H.z));
                o1.w += fmaf(d1, e1H.w, fmaf(d2, e2H.w, d3 * e3H.w));
                if ((row >> 2) == tx)     ((float*)&o0)[i & 3] += d0;
                if ((row >> 2) == tx + 8) ((float*)&o1)[i & 3] += d0;
            }
            if (toGlobal) {
                *(float4*)(gE3 + offL) = o0;
                *(float4*)(gE3 + offH) = o1;
            } else {
                *(float4*)(C + offL) = o0;
                *(float4*)(C + offH) = o1;
            }
        }
        if (toGlobal) __threadfence_block();
        hbar(m);
    }

    // ---- store (de-swizzle): result in s0 if nsq even, else s3 ----
    const float* src = (nsq & 1) ? s3 : s0;
#pragma unroll
    for (int q = 0; q < 16; q++) {
        const int e4 = t + q * 64;
        const int r = e4 >> 4, c4 = e4 & 15;
        O4[e4] = *(const float4*)(src + sw(r, c4));
    }
}

extern "C" void kernel_launch(void* const* d_in, const int* in_sizes, int n_in,
                              void* d_out, int out_size) {
    const float* R = (const float*)d_in[0];
    const float* G = (const float*)d_in[1];
    float* out = (float*)d_out;

    const int batch = in_sizes[0] / NN;                              // 8192
    const int grid = (batch + MATS_PER_CTA - 1) / MATS_PER_CTA;      // 2731
    const size_t smem = MATS_PER_CTA * 4 * NN * sizeof(float);       // 192 KB

    static bool attr_set = false;
    if (!attr_set) {
        cudaFuncSetAttribute(meg_update_kernel,
                             cudaFuncAttributeMaxDynamicSharedMemorySize,
                             (int)smem);
        attr_set = true;
    }

    meg_update_kernel<<<grid, THREADS, smem>>>(R, G, out, batch);
}